// round 13
// baseline (speedup 1.0000x reference)
#include <cuda_runtime.h>
#include <math.h>
#include <stdint.h>

static constexpr int N   = 100000;
static constexpr int E   = 1600000;
static constexpr int H   = 128;
static constexpr int OUTC = 64;
static constexpr int L   = 3;
static constexpr int G   = 3;
static constexpr int C   = 16;

// ---------------- device scratch (static globals; no runtime allocation) ----
__device__ int   g_cnt[N];
__device__ int   g_row[N];
__device__ int   g_cur[N];
__device__ int   g_csr[E];
__device__ float g_h[(size_t)L * N * H];  // per-layer pre-norm hidden (VQ input)
__device__ float g_zA[(size_t)N * H];     // normed activations (ping)
__device__ float g_zB[(size_t)N * H];     // normed activations (pong)
__device__ float g_cbn[L * G * C * H];
__device__ float g_loss;

// ---------------- packed f32x2 / async-copy helpers --------------------------
__device__ __forceinline__ unsigned long long fma2(unsigned long long a,
                                                   unsigned long long b,
                                                   unsigned long long c) {
    unsigned long long d;
    asm("fma.rn.f32x2 %0, %1, %2, %3;" : "=l"(d) : "l"(a), "l"(b), "l"(c));
    return d;
}
__device__ __forceinline__ unsigned long long packdup(float v) {
    unsigned long long p;
    asm("mov.b64 %0, {%1, %1};" : "=l"(p) : "f"(v));
    return p;
}
__device__ __forceinline__ uint32_t s2u(const void* p) {
    uint32_t a;
    asm("{ .reg .u64 t; cvta.to.shared.u64 t, %1; cvt.u32.u64 %0, t; }"
        : "=r"(a) : "l"(p));
    return a;
}
__device__ __forceinline__ void cpa16(uint32_t dst, const void* src, int bytes) {
    asm volatile("cp.async.ca.shared.global [%0], [%1], 16, %2;"
                 :: "r"(dst), "l"(src), "r"(bytes));
}
__device__ __forceinline__ void cpcommit() {
    asm volatile("cp.async.commit_group;" ::: "memory");
}
__device__ __forceinline__ void cpwait0() {
    asm volatile("cp.async.wait_group 0;" ::: "memory");
}

// ---------------- small utility kernels -------------------------------------
__global__ void k_zero(int* cnt, int* cur, float* loss) {
    int i = blockIdx.x * blockDim.x + threadIdx.x;
    if (i < N) { cnt[i] = 0; cur[i] = 0; }
    if (i == 0) *loss = 0.f;
}

__global__ void k_count(const int* __restrict__ ei, int* __restrict__ cnt) {
    int e = blockIdx.x * blockDim.x + threadIdx.x;
    if (e < E) atomicAdd(&cnt[ei[E + e]], 1);
}

// single-block exclusive scan of cnt[N] -> excl[N] (1024 threads, ~98 elems each)
// launch_bounds + unroll 1: keep regs <=64 so 1024-thread launch always fits.
__global__ __launch_bounds__(1024, 1)
void k_scan_one(const int* __restrict__ cnt, int* __restrict__ excl) {
    __shared__ int tot[1024];
    const int t = threadIdx.x;
    const int SEG = (N + 1023) / 1024;  // 98
    const int base = t * SEG;
    int s = 0;
    #pragma unroll 1
    for (int j = 0; j < SEG; j++) {
        int i = base + j;
        if (i < N) s += cnt[i];
    }
    tot[t] = s;
    __syncthreads();
    #pragma unroll 1
    for (int off = 1; off < 1024; off <<= 1) {
        int v = (t >= off) ? tot[t - off] : 0;
        __syncthreads();
        tot[t] += v;
        __syncthreads();
    }
    int run = tot[t] - s;  // exclusive prefix of this segment
    #pragma unroll 1
    for (int j = 0; j < SEG; j++) {
        int i = base + j;
        if (i < N) { excl[i] = run; run += cnt[i]; }
    }
}

// fill CSR slots with EDGE IDS (atomic claim order is irrelevant; sorted later)
__global__ void k_fill(const int* __restrict__ ei, const int* __restrict__ row,
                       int* __restrict__ cur, int* __restrict__ csr) {
    int e = blockIdx.x * blockDim.x + threadIdx.x;
    if (e < E) {
        int d = ei[E + e];
        int p = atomicAdd(&cur[d], 1);
        csr[row[d] + p] = e;
    }
}

// Canonicalize + map: sort each row's edge-id segment ascending (exact EDGE
// ORDER, matching reference segment_sum accumulation), then replace edge ids
// with source node ids. Deterministic + ULP-matched; segments are disjoint.
__global__ void k_sortmap(const int* __restrict__ row, const int* __restrict__ cnt,
                          int* __restrict__ csr, const int* __restrict__ ei) {
    int n = blockIdx.x * blockDim.x + threadIdx.x;
    if (n >= N) return;
    int st = row[n], dg = cnt[n];
    for (int i = 1; i < dg; i++) {
        int v = csr[st + i];
        int j = i - 1;
        while (j >= 0 && csr[st + j] > v) {
            csr[st + j + 1] = csr[st + j];
            j--;
        }
        csr[st + j + 1] = v;
    }
    for (int i = 0; i < dg; i++) csr[st + i] = ei[csr[st + i]];
}

// normalize all codebook rows once: 144 rows of 128 floats, 1 warp per row
__global__ void k_cbnorm(const float* __restrict__ cb, float* __restrict__ cbn) {
    int id = blockIdx.x;
    int lane = threadIdx.x;
    float4 v = reinterpret_cast<const float4*>(cb + (size_t)id * 128)[lane];
    float sq = v.x * v.x + v.y * v.y + v.z * v.z + v.w * v.w;
    #pragma unroll
    for (int o = 16; o > 0; o >>= 1) sq += __shfl_xor_sync(0xffffffffu, sq, o);
    float inv = 1.f / (sqrtf(sq) + 1e-8f);
    v.x *= inv; v.y *= inv; v.z *= inv; v.w *= inv;
    reinterpret_cast<float4*>(cbn + (size_t)id * 128)[lane] = v;
}

// ---------------- pipelined fused FFMA2 GEMM ---------------------------------
// C[N,BN] = A @ W1^T + bias  (DUAL: gather-mean(Z)@Wl^T + bias + Z@Wr^T).
// Software-pipelined, double-buffered smem. Gather: 4 independent neighbor
// loads in flight (MLP>=4), adds strictly sequential in edge order (bit-exact
// vs reference segment_sum).
template <int BN, bool DUAL, bool LNEPI, bool WRITE_H>
__global__ __launch_bounds__(256, 2)
void k_gemm3(const float* A1, const float* W1, const float* bias,
             const float* A2, const float* W2,
             const int* __restrict__ rowptr, const int* __restrict__ cnt,
             const int* __restrict__ csr,
             const float* lng, const float* lnb,
             float* Hout, float* Zout) {
    constexpr int BM = 128, BK = 32;
    constexpr int NP2 = BN / 32;          // col-pairs per thread
    constexpr int ASTR = 36;              // float stride, 16B-aligned rows
    constexpr int WSTR = BN + 4;          // float stride (even -> ull ok)
    constexpr int NC = DUAL ? 8 : 4;      // chunks: [agg x4] + [z x4] | [A x4]
    constexpr int WREG = (BN * BK) / 1024;// float4 W regs per thread

    extern __shared__ float sm[];
    float* A0 = sm;
    float* A1s = sm + BM * ASTR;
    float* W0 = sm + 2 * BM * ASTR;
    float* W1s = W0 + BK * WSTR;
    const uint32_t a0u = s2u(A0), a1u = s2u(A1s);

    const int tid = threadIdx.x;
    const int tx = tid & 15, ty = tid >> 4;
    const int row0 = blockIdx.x * BM;

    unsigned long long acc[8][NP2];
    #pragma unroll
    for (int r = 0; r < 8; r++)
        #pragma unroll
        for (int c = 0; c < NP2; c++) acc[r][c] = 0ull;

    float4 wregs[WREG];

    // ---- issue A chunk c into buffer b (cp.async or gather+STS) ----
    auto issueA = [&](int c, int b) {
        if (DUAL && c < 4) {
            const int kc = c * 32;
            const int sub = tid & 7, rloc = tid >> 3;
            float* dst = b ? A1s : A0;
            #pragma unroll
            for (int p = 0; p < 4; p++) {
                int r = rloc + p * 32;
                int gr = row0 + r;
                float ax = 0.f, ay = 0.f, az = 0.f, aw = 0.f;
                if (gr < N) {
                    int st = rowptr[gr];
                    int dg = cnt[gr];
                    int i = 0;
                    // 4 independent loads in flight; adds remain strictly
                    // sequential in edge order (numerics identical to 1-wide).
                    for (; i + 4 <= dg; i += 4) {
                        int s0 = csr[st + i];
                        int s1 = csr[st + i + 1];
                        int s2 = csr[st + i + 2];
                        int s3 = csr[st + i + 3];
                        float4 v0 = *reinterpret_cast<const float4*>(
                            &A2[(size_t)s0 * 128 + kc + sub * 4]);
                        float4 v1 = *reinterpret_cast<const float4*>(
                            &A2[(size_t)s1 * 128 + kc + sub * 4]);
                        float4 v2 = *reinterpret_cast<const float4*>(
                            &A2[(size_t)s2 * 128 + kc + sub * 4]);
                        float4 v3 = *reinterpret_cast<const float4*>(
                            &A2[(size_t)s3 * 128 + kc + sub * 4]);
                        ax += v0.x; ay += v0.y; az += v0.z; aw += v0.w;
                        ax += v1.x; ay += v1.y; az += v1.z; aw += v1.w;
                        ax += v2.x; ay += v2.y; az += v2.z; aw += v2.w;
                        ax += v3.x; ay += v3.y; az += v3.z; aw += v3.w;
                    }
                    for (; i < dg; i++) {
                        int s0 = csr[st + i];
                        float4 v0 = *reinterpret_cast<const float4*>(
                            &A2[(size_t)s0 * 128 + kc + sub * 4]);
                        ax += v0.x; ay += v0.y; az += v0.z; aw += v0.w;
                    }
                    float inv = dg > 0 ? 1.f / (float)dg : 0.f;
                    ax *= inv; ay *= inv; az *= inv; aw *= inv;
                }
                *reinterpret_cast<float4*>(&dst[r * ASTR + sub * 4]) =
                    make_float4(ax, ay, az, aw);
            }
        } else {
            const int kc = (DUAL ? (c - 4) : c) * 32;
            const float* A = DUAL ? A2 : A1;
            const uint32_t dst = b ? a1u : a0u;
            #pragma unroll
            for (int i = 0; i < 4; i++) {
                int idx = tid + i * 256;
                int r = idx >> 3;
                int k4 = (idx & 7) * 4;
                int gr = row0 + r;
                cpa16(dst + (uint32_t)(r * ASTR + k4) * 4,
                      &A[(size_t)gr * 128 + kc + k4], gr < N ? 16 : 0);
            }
        }
    };
    // ---- W chunk c: global -> regs ----
    auto ldgW = [&](int c) {
        const float* W = (DUAL && c >= 4) ? W2 : W1;
        const int kc = (DUAL ? (c & 3) : c) * 32;
        #pragma unroll
        for (int i = 0; i < WREG; i++) {
            int idx = tid + i * 256;
            int n = idx >> 3;
            int k4 = (idx & 7) * 4;
            wregs[i] = *reinterpret_cast<const float4*>(&W[(size_t)n * 128 + kc + k4]);
        }
    };
    // ---- W regs -> smem buffer b (transposed to [k][n]) ----
    auto stsW = [&](int b) {
        float* Wd = b ? W1s : W0;
        #pragma unroll
        for (int i = 0; i < WREG; i++) {
            int idx = tid + i * 256;
            int n = idx >> 3;
            int k4 = (idx & 7) * 4;
            Wd[(k4 + 0) * WSTR + n] = wregs[i].x;
            Wd[(k4 + 1) * WSTR + n] = wregs[i].y;
            Wd[(k4 + 2) * WSTR + n] = wregs[i].z;
            Wd[(k4 + 3) * WSTR + n] = wregs[i].w;
        }
    };

    // ---- prologue: chunk 0 ----
    issueA(0, 0);
    ldgW(0);
    stsW(0);
    cpcommit();

    int buf = 0;
    #pragma unroll 1
    for (int i = 0; i < NC; i++) {
        cpwait0();
        __syncthreads();
        if (i + 1 < NC) {
            issueA(i + 1, buf ^ 1);   // gather chunks also STS here (regs freed)
            ldgW(i + 1);
        }
        // ---- compute chunk i from buffer buf ----
        {
            const float* Ab = buf ? A1s : A0;
            const float* Wb = buf ? W1s : W0;
            #pragma unroll
            for (int k = 0; k < BK; k += 2) {
                unsigned long long wp0[NP2], wp1[NP2];
                const unsigned long long* wr0 =
                    reinterpret_cast<const unsigned long long*>(Wb + k * WSTR);
                const unsigned long long* wr1 =
                    reinterpret_cast<const unsigned long long*>(Wb + (k + 1) * WSTR);
                #pragma unroll
                for (int c = 0; c < NP2; c++) {
                    wp0[c] = wr0[tx + 16 * c];
                    wp1[c] = wr1[tx + 16 * c];
                }
                #pragma unroll
                for (int r = 0; r < 8; r++) {
                    float2 a = *reinterpret_cast<const float2*>(
                        &Ab[(ty * 8 + r) * ASTR + k]);
                    unsigned long long a0 = packdup(a.x);
                    unsigned long long a1 = packdup(a.y);
                    #pragma unroll
                    for (int c = 0; c < NP2; c++) {
                        acc[r][c] = fma2(a0, wp0[c], acc[r][c]);
                        acc[r][c] = fma2(a1, wp1[c], acc[r][c]);
                    }
                }
            }
        }
        if (i + 1 < NC) stsW(buf ^ 1);
        cpcommit();
        buf ^= 1;
    }

    // ---- epilogue ----
    float2 bv[NP2];
    #pragma unroll
    for (int c = 0; c < NP2; c++) {
        int col = 2 * tx + 32 * c;
        bv[c].x = bias[col];
        bv[c].y = bias[col + 1];
    }
    if (LNEPI) {
        float2 gv[NP2], btv[NP2];
        #pragma unroll
        for (int c = 0; c < NP2; c++) {
            int col = 2 * tx + 32 * c;
            gv[c].x = lng[col];  gv[c].y = lng[col + 1];
            btv[c].x = lnb[col]; btv[c].y = lnb[col + 1];
        }
        #pragma unroll
        for (int r = 0; r < 8; r++) {
            int gr = row0 + ty * 8 + r;
            float v[2 * NP2];
            float s = 0.f, q = 0.f;
            #pragma unroll
            for (int c = 0; c < NP2; c++) {
                float lo, hi;
                asm("mov.b64 {%0, %1}, %2;" : "=f"(lo), "=f"(hi) : "l"(acc[r][c]));
                lo += bv[c].x; hi += bv[c].y;
                v[2 * c] = lo; v[2 * c + 1] = hi;
                s += lo + hi;
                q += lo * lo + hi * hi;
            }
            #pragma unroll
            for (int o = 8; o > 0; o >>= 1) {
                s += __shfl_xor_sync(0xffffffffu, s, o);
                q += __shfl_xor_sync(0xffffffffu, q, o);
            }
            float m = s * (1.f / 128.f);
            float var = q * (1.f / 128.f) - m * m;
            float rs = rsqrtf(var + 1e-5f);
            if (gr < N) {
                #pragma unroll
                for (int c = 0; c < NP2; c++) {
                    int col = 2 * tx + 32 * c;
                    if (WRITE_H)
                        *reinterpret_cast<float2*>(&Hout[(size_t)gr * BN + col]) =
                            make_float2(v[2 * c], v[2 * c + 1]);
                    float z0 = fmaxf((v[2 * c]     - m) * rs * gv[c].x + btv[c].x, 0.f);
                    float z1 = fmaxf((v[2 * c + 1] - m) * rs * gv[c].y + btv[c].y, 0.f);
                    *reinterpret_cast<float2*>(&Zout[(size_t)gr * BN + col]) =
                        make_float2(z0, z1);
                }
            }
        }
    } else {
        #pragma unroll
        for (int r = 0; r < 8; r++) {
            int gr = row0 + ty * 8 + r;
            if (gr < N) {
                #pragma unroll
                for (int c = 0; c < NP2; c++) {
                    float lo, hi;
                    asm("mov.b64 {%0, %1}, %2;" : "=f"(lo), "=f"(hi) : "l"(acc[r][c]));
                    float2 o = make_float2(lo + bv[c].x, hi + bv[c].y);
                    *reinterpret_cast<float2*>(&Zout[(size_t)gr * BN + 2 * tx + 32 * c]) = o;
                }
            }
        }
    }
}

// ---------------- residual VQ: one node per warp, 3 stages fused ------------
__global__ void k_vq(const float* __restrict__ h, const float* __restrict__ cbn,
                     float* __restrict__ ids, int l, float* __restrict__ loss) {
    __shared__ float bl;
    if (threadIdx.x == 0) bl = 0.f;
    __syncthreads();
    int node = blockIdx.x * 8 + (threadIdx.x >> 5);
    int lane = threadIdx.x & 31;
    float4 r = reinterpret_cast<const float4*>(h + (size_t)node * 128)[lane];
    float lsum = 0.f;
    for (int q = 0; q < G; q++) {
        const float* cb = cbn + q * C * 128;
        float best = -1e30f;
        int bi = 0;
        #pragma unroll 4
        for (int c = 0; c < C; c++) {
            float4 w = reinterpret_cast<const float4*>(cb + (size_t)c * 128)[lane];
            float p = r.x * w.x + r.y * w.y + r.z * w.z + r.w * w.w;
            #pragma unroll
            for (int o = 16; o > 0; o >>= 1) p += __shfl_xor_sync(0xffffffffu, p, o);
            if (p > best) { best = p; bi = c; }  // '>' keeps first index (matches argmax)
        }
        float4 w = reinterpret_cast<const float4*>(cb + (size_t)bi * 128)[lane];
        r.x -= w.x; r.y -= w.y; r.z -= w.z; r.w -= w.w;
        lsum += r.x * r.x + r.y * r.y + r.z * r.z + r.w * r.w;
        if (lane == 0) ids[(size_t)node * (L * G) + l * G + q] = (float)bi;
    }
    #pragma unroll
    for (int o = 16; o > 0; o >>= 1) lsum += __shfl_xor_sync(0xffffffffu, lsum, o);
    if (lane == 0) atomicAdd(&bl, lsum);
    __syncthreads();
    if (threadIdx.x == 0) atomicAdd(loss, bl);
}

__global__ void k_fin(const float* __restrict__ loss, float* __restrict__ dst) {
    *dst = (*loss) * (0.25f / ((float)N * (float)H));
}

// ---------------- host orchestration ----------------------------------------
extern "C" void kernel_launch(void* const* d_in, const int* in_sizes, int n_in,
                              void* d_out, int out_size) {
    const float* x        = (const float*)d_in[0];
    const int*   ei       = (const int*)d_in[1];
    const float* lin1_w   = (const float*)d_in[2];
    const float* lin1_b   = (const float*)d_in[3];
    const float* norms_g  = (const float*)d_in[4];
    const float* norms_b  = (const float*)d_in[5];
    const float* convl_w  = (const float*)d_in[6];
    const float* convl_b  = (const float*)d_in[7];
    const float* convr_w  = (const float*)d_in[8];
    const float* codebooks= (const float*)d_in[9];
    const float* fnorm_g  = (const float*)d_in[10];
    const float* fnorm_b  = (const float*)d_in[11];
    const float* lin2_w   = (const float*)d_in[12];
    const float* lin2_b   = (const float*)d_in[13];
    float* out = (float*)d_out;

    int *cnt, *rowp, *cur, *csr;
    float *h, *zA, *zB, *cbn, *loss;
    cudaGetSymbolAddress((void**)&cnt,  g_cnt);
    cudaGetSymbolAddress((void**)&rowp, g_row);
    cudaGetSymbolAddress((void**)&cur,  g_cur);
    cudaGetSymbolAddress((void**)&csr,  g_csr);
    cudaGetSymbolAddress((void**)&h,    g_h);
    cudaGetSymbolAddress((void**)&zA,   g_zA);
    cudaGetSymbolAddress((void**)&zB,   g_zB);
    cudaGetSymbolAddress((void**)&cbn,  g_cbn);
    cudaGetSymbolAddress((void**)&loss, g_loss);

    // side streams + fork/join events (created once; graph capture replays nodes)
    static cudaStream_t sCSR = nullptr, sVQ = nullptr;
    static cudaEvent_t evF = nullptr, evCSR, evH0, evH1, evH2, evVQ;
    if (sCSR == nullptr) {
        cudaStreamCreateWithFlags(&sCSR, cudaStreamNonBlocking);
        cudaStreamCreateWithFlags(&sVQ,  cudaStreamNonBlocking);
        cudaEventCreateWithFlags(&evF,   cudaEventDisableTiming);
        cudaEventCreateWithFlags(&evCSR, cudaEventDisableTiming);
        cudaEventCreateWithFlags(&evH0,  cudaEventDisableTiming);
        cudaEventCreateWithFlags(&evH1,  cudaEventDisableTiming);
        cudaEventCreateWithFlags(&evH2,  cudaEventDisableTiming);
        cudaEventCreateWithFlags(&evVQ,  cudaEventDisableTiming);
    }
    cudaEvent_t evH[3] = {evH0, evH1, evH2};

    // smem: double-buffered A (plain float) + double-buffered W (transposed)
    constexpr int SMEM_H = (2 * 128 * 36 + 2 * 32 * 132) * 4;  // 70656 (BN=128)
    constexpr int SMEM_O = (2 * 128 * 36 + 2 * 32 * 68) * 4;   // 54272 (BN=64)
    cudaFuncSetAttribute((const void*)k_gemm3<128, false, true, false>,
                         cudaFuncAttributeMaxDynamicSharedMemorySize, SMEM_H);
    cudaFuncSetAttribute((const void*)k_gemm3<128, true, true, true>,
                         cudaFuncAttributeMaxDynamicSharedMemorySize, SMEM_H);
    cudaFuncSetAttribute((const void*)k_gemm3<64, false, false, false>,
                         cudaFuncAttributeMaxDynamicSharedMemorySize, SMEM_O);

    const int GB = (N + 127) / 128;     // 782 GEMM blocks
    const size_t NH = (size_t)N * H;

    // ---- launch order arranged so launch #6 (ncu -s 5 -c 1) = lin1 GEMM ----
    cudaEventRecord(evF, 0);
    cudaStreamWaitEvent(sCSR, evF, 0);

    k_cbnorm<<<L * G * C, 32>>>(codebooks, cbn);                      // #1 (main)
    k_zero<<<(N + 255) / 256, 256, 0, sCSR>>>(cnt, cur, loss);        // #2
    k_count<<<(E + 255) / 256, 256, 0, sCSR>>>(ei, cnt);              // #3
    k_scan_one<<<1, 1024, 0, sCSR>>>(cnt, rowp);                      // #4
    k_fill<<<(E + 255) / 256, 256, 0, sCSR>>>(ei, rowp, cur, csr);    // #5
    // lin1 + LayerNorm(norms0) + ReLU fused -> z0   (#6: profiled by ncu)
    k_gemm3<128, false, true, false><<<GB, 256, SMEM_H>>>(
        x, lin1_w, lin1_b, nullptr, nullptr,
        nullptr, nullptr, nullptr,
        norms_g, norms_b, nullptr, zA);                               // #6 (main)
    k_sortmap<<<(N + 255) / 256, 256, 0, sCSR>>>(rowp, cnt, csr, ei); // #7
    cudaEventRecord(evCSR, sCSR);

    // join: conv layers need the CSR
    cudaStreamWaitEvent(0, evCSR, 0);

    float* zin = zA;
    float* zout = zB;
    for (int l = 0; l < L; l++) {
        const float* lg = (l < L - 1) ? norms_g + (size_t)(l + 1) * H : fnorm_g;
        const float* lb = (l < L - 1) ? norms_b + (size_t)(l + 1) * H : fnorm_b;
        float* hl = h + (size_t)l * NH;   // per-layer slab: VQ reads while next GEMM runs
        k_gemm3<128, true, true, true><<<GB, 256, SMEM_H>>>(
            nullptr, convl_w + (size_t)l * H * H, convl_b + (size_t)l * H,
            zin, convr_w + (size_t)l * H * H,
            rowp, cnt, csr,
            lg, lb, hl, zout);
        // VQ on side stream, overlapping the next layer's GEMM / lin2
        cudaEventRecord(evH[l], 0);
        cudaStreamWaitEvent(sVQ, evH[l], 0);
        k_vq<<<N / 8, 256, 0, sVQ>>>(hl, cbn + (size_t)l * G * C * H,
                                     out + (size_t)N * OUTC + 1, l, loss);
        float* t = zin; zin = zout; zout = t;
    }

    // lin2 on final normed activations (independent of VQ stream)
    k_gemm3<64, false, false, false><<<GB, 256, SMEM_O>>>(
        zin, lin2_w, lin2_b, nullptr, nullptr,
        nullptr, nullptr, nullptr,
        nullptr, nullptr, nullptr, out);

    // join VQ stream, then finalize loss
    cudaEventRecord(evVQ, sVQ);
    cudaStreamWaitEvent(0, evVQ, 0);
    k_fin<<<1, 1>>>(loss, out + (size_t)N * OUTC);
}

// round 14
// speedup vs baseline: 1.3085x; 1.3085x over previous
#include <cuda_runtime.h>
#include <math.h>
#include <stdint.h>

static constexpr int N   = 100000;
static constexpr int E   = 1600000;
static constexpr int H   = 128;
static constexpr int OUTC = 64;
static constexpr int L   = 3;
static constexpr int G   = 3;
static constexpr int C   = 16;

// ---------------- device scratch (static globals; no runtime allocation) ----
__device__ int   g_cnt[N];
__device__ int   g_row[N];
__device__ int   g_cur[N];
__device__ int   g_bsum[128];
__device__ int   g_csr[E];
__device__ float g_h[(size_t)L * N * H];  // per-layer pre-norm hidden (VQ input)
__device__ float g_zA[(size_t)N * H];     // normed activations (ping)
__device__ float g_zB[(size_t)N * H];     // normed activations (pong)
__device__ float g_agg[(size_t)N * H];    // mean-aggregated neighbors
__device__ float g_cbn[L * G * C * H];
__device__ float g_loss;

// ---------------- packed f32x2 / async-copy helpers --------------------------
__device__ __forceinline__ unsigned long long fma2(unsigned long long a,
                                                   unsigned long long b,
                                                   unsigned long long c) {
    unsigned long long d;
    asm("fma.rn.f32x2 %0, %1, %2, %3;" : "=l"(d) : "l"(a), "l"(b), "l"(c));
    return d;
}
__device__ __forceinline__ unsigned long long packdup(float v) {
    unsigned long long p;
    asm("mov.b64 %0, {%1, %1};" : "=l"(p) : "f"(v));
    return p;
}
__device__ __forceinline__ uint32_t s2u(const void* p) {
    uint32_t a;
    asm("{ .reg .u64 t; cvta.to.shared.u64 t, %1; cvt.u32.u64 %0, t; }"
        : "=r"(a) : "l"(p));
    return a;
}
__device__ __forceinline__ void cpa16(uint32_t dst, const void* src, int bytes) {
    asm volatile("cp.async.ca.shared.global [%0], [%1], 16, %2;"
                 :: "r"(dst), "l"(src), "r"(bytes));
}
__device__ __forceinline__ void cpcommit() {
    asm volatile("cp.async.commit_group;" ::: "memory");
}
__device__ __forceinline__ void cpwait0() {
    asm volatile("cp.async.wait_group 0;" ::: "memory");
}

// ---------------- small utility kernels -------------------------------------
__global__ void k_zero(int* cnt, int* cur, float* loss) {
    int i = blockIdx.x * blockDim.x + threadIdx.x;
    if (i < N) { cnt[i] = 0; cur[i] = 0; }
    if (i == 0) *loss = 0.f;
}

__global__ void k_count(const int* __restrict__ ei, int* __restrict__ cnt) {
    int e = blockIdx.x * blockDim.x + threadIdx.x;
    if (e < E) atomicAdd(&cnt[ei[E + e]], 1);
}

// multi-block scan (round-11 version: fast, low-reg)
__global__ void k_scan_block(const int* __restrict__ cnt, int* __restrict__ excl,
                             int* __restrict__ bsum) {
    __shared__ int s[1024];
    int i = blockIdx.x * 1024 + threadIdx.x;
    int v = (i < N) ? cnt[i] : 0;
    s[threadIdx.x] = v;
    __syncthreads();
    for (int off = 1; off < 1024; off <<= 1) {
        int t = (threadIdx.x >= off) ? s[threadIdx.x - off] : 0;
        __syncthreads();
        s[threadIdx.x] += t;
        __syncthreads();
    }
    if (i < N) excl[i] = s[threadIdx.x] - v;
    if (threadIdx.x == 1023) bsum[blockIdx.x] = s[1023];
}

__global__ void k_scan_sums(int* __restrict__ bsum, int nb) {
    __shared__ int s[128];
    int t = threadIdx.x;
    int v = (t < nb) ? bsum[t] : 0;
    s[t] = v;
    __syncthreads();
    for (int off = 1; off < 128; off <<= 1) {
        int u = (t >= off) ? s[t - off] : 0;
        __syncthreads();
        s[t] += u;
        __syncthreads();
    }
    if (t < nb) bsum[t] = s[t] - v;  // exclusive
}

__global__ void k_scan_add(int* __restrict__ excl, const int* __restrict__ bsum) {
    int i = blockIdx.x * 1024 + threadIdx.x;
    if (i < N) excl[i] += bsum[blockIdx.x];
}

// fill CSR slots with EDGE IDS (atomic claim order is irrelevant; sorted later)
__global__ void k_fill(const int* __restrict__ ei, const int* __restrict__ row,
                       int* __restrict__ cur, int* __restrict__ csr) {
    int e = blockIdx.x * blockDim.x + threadIdx.x;
    if (e < E) {
        int d = ei[E + e];
        int p = atomicAdd(&cur[d], 1);
        csr[row[d] + p] = e;
    }
}

// Canonicalize + map: sort each row's edge-id segment ascending (exact EDGE
// ORDER, matching reference segment_sum accumulation), then replace edge ids
// with source node ids. Deterministic + ULP-matched; segments are disjoint.
__global__ void k_sortmap(const int* __restrict__ row, const int* __restrict__ cnt,
                          int* __restrict__ csr, const int* __restrict__ ei) {
    int n = blockIdx.x * blockDim.x + threadIdx.x;
    if (n >= N) return;
    int st = row[n], dg = cnt[n];
    for (int i = 1; i < dg; i++) {
        int v = csr[st + i];
        int j = i - 1;
        while (j >= 0 && csr[st + j] > v) {
            csr[st + j + 1] = csr[st + j];
            j--;
        }
        csr[st + j + 1] = v;
    }
    for (int i = 0; i < dg; i++) csr[st + i] = ei[csr[st + i]];
}

// normalize all codebook rows once: 144 rows of 128 floats, 1 warp per row
__global__ void k_cbnorm(const float* __restrict__ cb, float* __restrict__ cbn) {
    int id = blockIdx.x;
    int lane = threadIdx.x;
    float4 v = reinterpret_cast<const float4*>(cb + (size_t)id * 128)[lane];
    float sq = v.x * v.x + v.y * v.y + v.z * v.z + v.w * v.w;
    #pragma unroll
    for (int o = 16; o > 0; o >>= 1) sq += __shfl_xor_sync(0xffffffffu, sq, o);
    float inv = 1.f / (sqrtf(sq) + 1e-8f);
    v.x *= inv; v.y *= inv; v.z *= inv; v.w *= inv;
    reinterpret_cast<float4*>(cbn + (size_t)id * 128)[lane] = v;
}

// ---------------- mean aggregation: one node per warp -----------------------
// Massively parallel L2 gather (no phase-locking with compute). Adds are
// strictly sequential in edge order per component -> bit-identical to the
// reference segment_sum accumulation. 4 neighbor loads in flight.
__global__ __launch_bounds__(256, 8)
void k_agg(const float* __restrict__ z, const int* __restrict__ rowptr,
           const int* __restrict__ cnt, const int* __restrict__ csr,
           float* __restrict__ agg) {
    int node = blockIdx.x * 8 + (threadIdx.x >> 5);
    int lane = threadIdx.x & 31;
    if (node >= N) return;
    int st = rowptr[node];
    int dg = cnt[node];
    float ax = 0.f, ay = 0.f, az = 0.f, aw = 0.f;
    int i = 0;
    for (; i + 4 <= dg; i += 4) {
        int s0 = csr[st + i];
        int s1 = csr[st + i + 1];
        int s2 = csr[st + i + 2];
        int s3 = csr[st + i + 3];
        float4 v0 = reinterpret_cast<const float4*>(z + (size_t)s0 * 128)[lane];
        float4 v1 = reinterpret_cast<const float4*>(z + (size_t)s1 * 128)[lane];
        float4 v2 = reinterpret_cast<const float4*>(z + (size_t)s2 * 128)[lane];
        float4 v3 = reinterpret_cast<const float4*>(z + (size_t)s3 * 128)[lane];
        ax += v0.x; ay += v0.y; az += v0.z; aw += v0.w;
        ax += v1.x; ay += v1.y; az += v1.z; aw += v1.w;
        ax += v2.x; ay += v2.y; az += v2.z; aw += v2.w;
        ax += v3.x; ay += v3.y; az += v3.z; aw += v3.w;
    }
    for (; i < dg; i++) {
        int s0 = csr[st + i];
        float4 v0 = reinterpret_cast<const float4*>(z + (size_t)s0 * 128)[lane];
        ax += v0.x; ay += v0.y; az += v0.z; aw += v0.w;
    }
    float inv = dg > 0 ? 1.f / (float)dg : 0.f;
    reinterpret_cast<float4*>(agg + (size_t)node * 128)[lane] =
        make_float4(ax * inv, ay * inv, az * inv, aw * inv);
}

// ---------------- pipelined fused FFMA2 GEMM ---------------------------------
// C[N,BN] = A1 @ W1^T + bias  (DUAL: A1@W1^T + bias + A2@W2^T, chunks 0-3 from
// A1/W1, 4-7 from A2/W2). ALL A chunks via cp.async -> uniform double-buffered
// pipeline; no synchronous gather inside the mainloop.
// LNEPI: LayerNorm+ReLU epilogue; WRITE_H stores pre-norm h.
template <int BN, bool DUAL, bool LNEPI, bool WRITE_H>
__global__ __launch_bounds__(256, 2)
void k_gemm3(const float* A1, const float* W1, const float* bias,
             const float* A2, const float* W2,
             const float* lng, const float* lnb,
             float* Hout, float* Zout) {
    constexpr int BM = 128, BK = 32;
    constexpr int NP2 = BN / 32;          // col-pairs per thread
    constexpr int ASTR = 36;              // float stride, 16B-aligned rows
    constexpr int WSTR = BN + 4;          // float stride (even -> ull ok)
    constexpr int NC = DUAL ? 8 : 4;      // chunks
    constexpr int WREG = (BN * BK) / 1024;// float4 W regs per thread

    extern __shared__ float sm[];
    float* A0 = sm;
    float* A1s = sm + BM * ASTR;
    float* W0 = sm + 2 * BM * ASTR;
    float* W1s = W0 + BK * WSTR;
    const uint32_t a0u = s2u(A0), a1u = s2u(A1s);

    const int tid = threadIdx.x;
    const int tx = tid & 15, ty = tid >> 4;
    const int row0 = blockIdx.x * BM;

    unsigned long long acc[8][NP2];
    #pragma unroll
    for (int r = 0; r < 8; r++)
        #pragma unroll
        for (int c = 0; c < NP2; c++) acc[r][c] = 0ull;

    float4 wregs[WREG];

    // ---- A chunk c -> buffer b via cp.async ----
    auto issueA = [&](int c, int b) {
        const float* A = (DUAL && c >= 4) ? A2 : A1;
        const int kc = (DUAL ? (c & 3) : c) * 32;
        const uint32_t dst = b ? a1u : a0u;
        #pragma unroll
        for (int i = 0; i < 4; i++) {
            int idx = tid + i * 256;
            int r = idx >> 3;
            int k4 = (idx & 7) * 4;
            int gr = row0 + r;
            cpa16(dst + (uint32_t)(r * ASTR + k4) * 4,
                  &A[(size_t)gr * 128 + kc + k4], gr < N ? 16 : 0);
        }
    };
    // ---- W chunk c: global -> regs ----
    auto ldgW = [&](int c) {
        const float* W = (DUAL && c >= 4) ? W2 : W1;
        const int kc = (DUAL ? (c & 3) : c) * 32;
        #pragma unroll
        for (int i = 0; i < WREG; i++) {
            int idx = tid + i * 256;
            int n = idx >> 3;
            int k4 = (idx & 7) * 4;
            wregs[i] = *reinterpret_cast<const float4*>(&W[(size_t)n * 128 + kc + k4]);
        }
    };
    // ---- W regs -> smem buffer b (transposed to [k][n]) ----
    auto stsW = [&](int b) {
        float* Wd = b ? W1s : W0;
        #pragma unroll
        for (int i = 0; i < WREG; i++) {
            int idx = tid + i * 256;
            int n = idx >> 3;
            int k4 = (idx & 7) * 4;
            Wd[(k4 + 0) * WSTR + n] = wregs[i].x;
            Wd[(k4 + 1) * WSTR + n] = wregs[i].y;
            Wd[(k4 + 2) * WSTR + n] = wregs[i].z;
            Wd[(k4 + 3) * WSTR + n] = wregs[i].w;
        }
    };

    // ---- prologue: chunk 0 ----
    issueA(0, 0);
    ldgW(0);
    stsW(0);
    cpcommit();

    int buf = 0;
    #pragma unroll 1
    for (int i = 0; i < NC; i++) {
        cpwait0();
        __syncthreads();
        if (i + 1 < NC) {
            issueA(i + 1, buf ^ 1);
            ldgW(i + 1);
        }
        // ---- compute chunk i from buffer buf ----
        {
            const float* Ab = buf ? A1s : A0;
            const float* Wb = buf ? W1s : W0;
            #pragma unroll
            for (int k = 0; k < BK; k += 2) {
                unsigned long long wp0[NP2], wp1[NP2];
                const unsigned long long* wr0 =
                    reinterpret_cast<const unsigned long long*>(Wb + k * WSTR);
                const unsigned long long* wr1 =
                    reinterpret_cast<const unsigned long long*>(Wb + (k + 1) * WSTR);
                #pragma unroll
                for (int c = 0; c < NP2; c++) {
                    wp0[c] = wr0[tx + 16 * c];
                    wp1[c] = wr1[tx + 16 * c];
                }
                #pragma unroll
                for (int r = 0; r < 8; r++) {
                    float2 a = *reinterpret_cast<const float2*>(
                        &Ab[(ty * 8 + r) * ASTR + k]);
                    unsigned long long a0 = packdup(a.x);
                    unsigned long long a1 = packdup(a.y);
                    #pragma unroll
                    for (int c = 0; c < NP2; c++) {
                        acc[r][c] = fma2(a0, wp0[c], acc[r][c]);
                        acc[r][c] = fma2(a1, wp1[c], acc[r][c]);
                    }
                }
            }
        }
        if (i + 1 < NC) stsW(buf ^ 1);
        cpcommit();
        buf ^= 1;
    }

    // ---- epilogue ----
    float2 bv[NP2];
    #pragma unroll
    for (int c = 0; c < NP2; c++) {
        int col = 2 * tx + 32 * c;
        bv[c].x = bias[col];
        bv[c].y = bias[col + 1];
    }
    if (LNEPI) {
        float2 gv[NP2], btv[NP2];
        #pragma unroll
        for (int c = 0; c < NP2; c++) {
            int col = 2 * tx + 32 * c;
            gv[c].x = lng[col];  gv[c].y = lng[col + 1];
            btv[c].x = lnb[col]; btv[c].y = lnb[col + 1];
        }
        #pragma unroll
        for (int r = 0; r < 8; r++) {
            int gr = row0 + ty * 8 + r;
            float v[2 * NP2];
            float s = 0.f, q = 0.f;
            #pragma unroll
            for (int c = 0; c < NP2; c++) {
                float lo, hi;
                asm("mov.b64 {%0, %1}, %2;" : "=f"(lo), "=f"(hi) : "l"(acc[r][c]));
                lo += bv[c].x; hi += bv[c].y;
                v[2 * c] = lo; v[2 * c + 1] = hi;
                s += lo + hi;
                q += lo * lo + hi * hi;
            }
            #pragma unroll
            for (int o = 8; o > 0; o >>= 1) {
                s += __shfl_xor_sync(0xffffffffu, s, o);
                q += __shfl_xor_sync(0xffffffffu, q, o);
            }
            float m = s * (1.f / 128.f);
            float var = q * (1.f / 128.f) - m * m;
            float rs = rsqrtf(var + 1e-5f);
            if (gr < N) {
                #pragma unroll
                for (int c = 0; c < NP2; c++) {
                    int col = 2 * tx + 32 * c;
                    if (WRITE_H)
                        *reinterpret_cast<float2*>(&Hout[(size_t)gr * BN + col]) =
                            make_float2(v[2 * c], v[2 * c + 1]);
                    float z0 = fmaxf((v[2 * c]     - m) * rs * gv[c].x + btv[c].x, 0.f);
                    float z1 = fmaxf((v[2 * c + 1] - m) * rs * gv[c].y + btv[c].y, 0.f);
                    *reinterpret_cast<float2*>(&Zout[(size_t)gr * BN + col]) =
                        make_float2(z0, z1);
                }
            }
        }
    } else {
        #pragma unroll
        for (int r = 0; r < 8; r++) {
            int gr = row0 + ty * 8 + r;
            if (gr < N) {
                #pragma unroll
                for (int c = 0; c < NP2; c++) {
                    float lo, hi;
                    asm("mov.b64 {%0, %1}, %2;" : "=f"(lo), "=f"(hi) : "l"(acc[r][c]));
                    float2 o = make_float2(lo + bv[c].x, hi + bv[c].y);
                    *reinterpret_cast<float2*>(&Zout[(size_t)gr * BN + 2 * tx + 32 * c]) = o;
                }
            }
        }
    }
}

// ---------------- residual VQ: one node per warp, 3 stages fused ------------
__global__ void k_vq(const float* __restrict__ h, const float* __restrict__ cbn,
                     float* __restrict__ ids, int l, float* __restrict__ loss) {
    __shared__ float bl;
    if (threadIdx.x == 0) bl = 0.f;
    __syncthreads();
    int node = blockIdx.x * 8 + (threadIdx.x >> 5);
    int lane = threadIdx.x & 31;
    float4 r = reinterpret_cast<const float4*>(h + (size_t)node * 128)[lane];
    float lsum = 0.f;
    for (int q = 0; q < G; q++) {
        const float* cb = cbn + q * C * 128;
        float best = -1e30f;
        int bi = 0;
        #pragma unroll 4
        for (int c = 0; c < C; c++) {
            float4 w = reinterpret_cast<const float4*>(cb + (size_t)c * 128)[lane];
            float p = r.x * w.x + r.y * w.y + r.z * w.z + r.w * w.w;
            #pragma unroll
            for (int o = 16; o > 0; o >>= 1) p += __shfl_xor_sync(0xffffffffu, p, o);
            if (p > best) { best = p; bi = c; }  // '>' keeps first index (matches argmax)
        }
        float4 w = reinterpret_cast<const float4*>(cb + (size_t)bi * 128)[lane];
        r.x -= w.x; r.y -= w.y; r.z -= w.z; r.w -= w.w;
        lsum += r.x * r.x + r.y * r.y + r.z * r.z + r.w * r.w;
        if (lane == 0) ids[(size_t)node * (L * G) + l * G + q] = (float)bi;
    }
    #pragma unroll
    for (int o = 16; o > 0; o >>= 1) lsum += __shfl_xor_sync(0xffffffffu, lsum, o);
    if (lane == 0) atomicAdd(&bl, lsum);
    __syncthreads();
    if (threadIdx.x == 0) atomicAdd(loss, bl);
}

__global__ void k_fin(const float* __restrict__ loss, float* __restrict__ dst) {
    *dst = (*loss) * (0.25f / ((float)N * (float)H));
}

// ---------------- host orchestration ----------------------------------------
extern "C" void kernel_launch(void* const* d_in, const int* in_sizes, int n_in,
                              void* d_out, int out_size) {
    const float* x        = (const float*)d_in[0];
    const int*   ei       = (const int*)d_in[1];
    const float* lin1_w   = (const float*)d_in[2];
    const float* lin1_b   = (const float*)d_in[3];
    const float* norms_g  = (const float*)d_in[4];
    const float* norms_b  = (const float*)d_in[5];
    const float* convl_w  = (const float*)d_in[6];
    const float* convl_b  = (const float*)d_in[7];
    const float* convr_w  = (const float*)d_in[8];
    const float* codebooks= (const float*)d_in[9];
    const float* fnorm_g  = (const float*)d_in[10];
    const float* fnorm_b  = (const float*)d_in[11];
    const float* lin2_w   = (const float*)d_in[12];
    const float* lin2_b   = (const float*)d_in[13];
    float* out = (float*)d_out;

    int *cnt, *rowp, *cur, *bsum, *csr;
    float *h, *zA, *zB, *agg, *cbn, *loss;
    cudaGetSymbolAddress((void**)&cnt,  g_cnt);
    cudaGetSymbolAddress((void**)&rowp, g_row);
    cudaGetSymbolAddress((void**)&cur,  g_cur);
    cudaGetSymbolAddress((void**)&bsum, g_bsum);
    cudaGetSymbolAddress((void**)&csr,  g_csr);
    cudaGetSymbolAddress((void**)&h,    g_h);
    cudaGetSymbolAddress((void**)&zA,   g_zA);
    cudaGetSymbolAddress((void**)&zB,   g_zB);
    cudaGetSymbolAddress((void**)&agg,  g_agg);
    cudaGetSymbolAddress((void**)&cbn,  g_cbn);
    cudaGetSymbolAddress((void**)&loss, g_loss);

    // side streams + fork/join events (created once; graph capture replays nodes)
    static cudaStream_t sCSR = nullptr, sVQ = nullptr;
    static cudaEvent_t evF = nullptr, evCSR, evH0, evH1, evH2, evVQ;
    if (sCSR == nullptr) {
        cudaStreamCreateWithFlags(&sCSR, cudaStreamNonBlocking);
        cudaStreamCreateWithFlags(&sVQ,  cudaStreamNonBlocking);
        cudaEventCreateWithFlags(&evF,   cudaEventDisableTiming);
        cudaEventCreateWithFlags(&evCSR, cudaEventDisableTiming);
        cudaEventCreateWithFlags(&evH0,  cudaEventDisableTiming);
        cudaEventCreateWithFlags(&evH1,  cudaEventDisableTiming);
        cudaEventCreateWithFlags(&evH2,  cudaEventDisableTiming);
        cudaEventCreateWithFlags(&evVQ,  cudaEventDisableTiming);
    }
    cudaEvent_t evH[3] = {evH0, evH1, evH2};

    // smem: double-buffered A (plain float) + double-buffered W (transposed)
    constexpr int SMEM_H = (2 * 128 * 36 + 2 * 32 * 132) * 4;  // 70656 (BN=128)
    constexpr int SMEM_O = (2 * 128 * 36 + 2 * 32 * 68) * 4;   // 54272 (BN=64)
    cudaFuncSetAttribute((const void*)k_gemm3<128, false, true, false>,
                         cudaFuncAttributeMaxDynamicSharedMemorySize, SMEM_H);
    cudaFuncSetAttribute((const void*)k_gemm3<128, true, true, true>,
                         cudaFuncAttributeMaxDynamicSharedMemorySize, SMEM_H);
    cudaFuncSetAttribute((const void*)k_gemm3<64, false, false, false>,
                         cudaFuncAttributeMaxDynamicSharedMemorySize, SMEM_O);

    const int NB = (N + 1023) / 1024;   // 98
    const int GB = (N + 127) / 128;     // 782 GEMM blocks
    const size_t NH = (size_t)N * H;

    // ---- fork: CSR build chain runs concurrently with cbnorm + lin1 ----
    cudaEventRecord(evF, 0);
    cudaStreamWaitEvent(sCSR, evF, 0);
    k_zero<<<(N + 255) / 256, 256, 0, sCSR>>>(cnt, cur, loss);
    k_count<<<(E + 255) / 256, 256, 0, sCSR>>>(ei, cnt);
    k_scan_block<<<NB, 1024, 0, sCSR>>>(cnt, rowp, bsum);
    k_scan_sums<<<1, 128, 0, sCSR>>>(bsum, NB);
    k_scan_add<<<NB, 1024, 0, sCSR>>>(rowp, bsum);
    k_fill<<<(E + 255) / 256, 256, 0, sCSR>>>(ei, rowp, cur, csr);
    k_sortmap<<<(N + 255) / 256, 256, 0, sCSR>>>(rowp, cnt, csr, ei);
    cudaEventRecord(evCSR, sCSR);

    // ---- main stream: codebook norm + lin1 (+LN0+ReLU) -> z0 ----
    k_cbnorm<<<L * G * C, 32>>>(codebooks, cbn);
    k_gemm3<128, false, true, false><<<GB, 256, SMEM_H>>>(
        x, lin1_w, lin1_b, nullptr, nullptr,
        norms_g, norms_b, nullptr, zA);

    // join: conv layers need the CSR
    cudaStreamWaitEvent(0, evCSR, 0);

    float* zin = zA;
    float* zout = zB;
    for (int l = 0; l < L; l++) {
        const float* lg = (l < L - 1) ? norms_g + (size_t)(l + 1) * H : fnorm_g;
        const float* lb = (l < L - 1) ? norms_b + (size_t)(l + 1) * H : fnorm_b;
        float* hl = h + (size_t)l * NH;   // per-layer slab: VQ reads while next GEMM runs
        // separate high-parallelism mean aggregation (bit-identical edge order)
        k_agg<<<(N + 7) / 8, 256>>>(zin, rowp, cnt, csr, agg);
        // clean all-cp.async DUAL GEMM: agg@Wl + bias + zin@Wr -> h; LN+ReLU -> zout
        k_gemm3<128, true, true, true><<<GB, 256, SMEM_H>>>(
            agg, convl_w + (size_t)l * H * H, convl_b + (size_t)l * H,
            zin, convr_w + (size_t)l * H * H,
            lg, lb, hl, zout);
        // VQ on side stream, overlapping the next layer's agg/GEMM
        cudaEventRecord(evH[l], 0);
        cudaStreamWaitEvent(sVQ, evH[l], 0);
        k_vq<<<N / 8, 256, 0, sVQ>>>(hl, cbn + (size_t)l * G * C * H,
                                     out + (size_t)N * OUTC + 1, l, loss);
        float* t = zin; zin = zout; zout = t;
    }

    // lin2 on final normed activations (independent of VQ stream)
    k_gemm3<64, false, false, false><<<GB, 256, SMEM_O>>>(
        zin, lin2_w, lin2_b, nullptr, nullptr,
        nullptr, nullptr, nullptr, out);

    // join VQ stream, then finalize loss
    cudaEventRecord(evVQ, sVQ);
    cudaStreamWaitEvent(0, evVQ, 0);
    k_fin<<<1, 1>>>(loss, out + (size_t)N * OUTC);
}